// round 9
// baseline (speedup 1.0000x reference)
#include <cuda_runtime.h>
#include <math.h>

#define NH 2
#define NB 2048
#define NM 64
#define ND 16
#define NREL 32

// Fused kernel: 1024 blocks x 256 threads; each block handles 2 b's CONCURRENTLY.
// Warps 0-3 process bb=0, warps 4-7 process bb=1 (independent half-blocks).
// Phase A: q[bb][r][j] = sum_i R[r][i][j]*item[bb][i] (vectorized, L2/L1-hot).
// Phase B: R3/R7-proven per-pass quad-split gathers + softmax.
__global__ __launch_bounds__(256)
void ripple_fused_kernel(const int* __restrict__ items,
                         const int* __restrict__ heads,
                         const int* __restrict__ rels,
                         const int* __restrict__ tails,
                         const float* __restrict__ ent,
                         const float* __restrict__ relm,
                         float* __restrict__ out)
{
    const int b0   = blockIdx.x * 2;
    const int t    = threadIdx.x;        // 0..255
    const int bb   = t >> 7;             // which b this half-block owns
    const int tl   = t & 127;            // thread-in-half 0..127
    const int lane = t & 31;
    const int widh = tl >> 5;            // warp-in-half 0..3
    const int sub  = t & 3;              // position within quad
    const int quad = tl >> 2;            // 0..31

    __shared__ __align__(16) float  item_s[2][ND];
    __shared__ __align__(16) float4 q_s[2][NREL * 4];   // [bb][r*4+jg]
    __shared__ float logit_s[2][NH * NM];
    __shared__ float td_s[2][NH * NM];
    __shared__ float red_s[2][8];

    // ---- Phase A0: load both item embeddings (32 floats) ----
    if (t < 2 * ND) {
        const int ib = t >> 4;
        const int d  = t & 15;
        item_s[ib][d] = ent[(size_t)items[b0 + ib] * ND + d];
    }
    __syncthreads();

    // ---- Phase A1: q-precompute; thread t owns (bb, r = tl>>2, jg = tl&3) ----
    {
        const int r  = tl >> 2;
        const int jg = tl & 3;
        const float4* relm4 = (const float4*)relm;

        float4 a = make_float4(0.f, 0.f, 0.f, 0.f);
        #pragma unroll
        for (int i = 0; i < ND; i++) {
            float4 Rv = relm4[r * 64 + i * 4 + jg];   // same addrs both halves -> L1 hit
            float s = item_s[bb][i];
            a.x += s * Rv.x; a.y += s * Rv.y; a.z += s * Rv.z; a.w += s * Rv.w;
        }
        q_s[bb][tl] = a;    // tl == r*4+jg
    }
    __syncthreads();

    const float4* ent4 = (const float4*)ent;
    const int     b    = b0 + bb;
    const float4  iv   = ((const float4*)item_s[bb])[sub];

    // ---- Phase B: per-pass quad-split gathers (proven structure) ----
    #pragma unroll
    for (int pass = 0; pass < 4; pass++) {
        const int s    = pass * 32 + quad;       // slot 0..127
        const int hop  = s >> 6;
        const int m    = s & 63;
        const int gidx = hop * (NB * NM) + b * NM + m;

        const int hidx = heads[gidx];
        const int ridx = rels[gidx];
        const int tidx = tails[gidx];

        float4 hv = ent4[(size_t)hidx * 4 + sub];
        float4 tv = ent4[(size_t)tidx * 4 + sub];
        float4 qv = q_s[bb][ridx * 4 + sub];

        float pl = qv.x * hv.x + qv.y * hv.y + qv.z * hv.z + qv.w * hv.w;
        float pt = iv.x * tv.x + iv.y * tv.y + iv.z * tv.z + iv.w * tv.w;

        pl += __shfl_xor_sync(0xffffffffu, pl, 1);
        pl += __shfl_xor_sync(0xffffffffu, pl, 2);
        pt += __shfl_xor_sync(0xffffffffu, pt, 1);
        pt += __shfl_xor_sync(0xffffffffu, pt, 2);

        logit_s[bb][s] = pl;
        td_s[bb][s]    = pt;
    }
    __syncthreads();

    // ---- softmax over 64 slots per hop; thread tl owns slot tl of its half ----
    const int hop = tl >> 6;
    float logit = logit_s[bb][tl];
    float td    = td_s[bb][tl];

    float mx = logit;
    #pragma unroll
    for (int o = 16; o > 0; o >>= 1)
        mx = fmaxf(mx, __shfl_xor_sync(0xffffffffu, mx, o));
    if (lane == 0) red_s[bb][widh] = mx;
    __syncthreads();
    mx = fmaxf(red_s[bb][hop * 2], red_s[bb][hop * 2 + 1]);

    float e = __expf(logit - mx);
    float sm = e;
    #pragma unroll
    for (int o = 16; o > 0; o >>= 1)
        sm += __shfl_xor_sync(0xffffffffu, sm, o);
    if (lane == 0) red_s[bb][4 + widh] = sm;
    __syncthreads();
    sm = red_s[bb][4 + hop * 2] + red_s[bb][4 + hop * 2 + 1];

    const float pi = e / sm;

    // ---- contribution: pi * (tail . item); reduce over this half's 128 threads ----
    float c = pi * td;
    #pragma unroll
    for (int o = 16; o > 0; o >>= 1)
        c += __shfl_xor_sync(0xffffffffu, c, o);
    __syncthreads();                 // protect red_s reuse
    if (lane == 0) red_s[bb][widh] = c;
    __syncthreads();

    if (tl == 0) {
        float total = red_s[bb][0] + red_s[bb][1] + red_s[bb][2] + red_s[bb][3];
        out[b] = 1.f / (1.f + __expf(-total));
    }
}

extern "C" void kernel_launch(void* const* d_in, const int* in_sizes, int n_in,
                              void* d_out, int out_size)
{
    const int*   items = (const int*)d_in[0];
    const int*   heads = (const int*)d_in[1];
    const int*   rels  = (const int*)d_in[2];
    const int*   tails = (const int*)d_in[3];
    const float* ent   = (const float*)d_in[4];
    const float* relm  = (const float*)d_in[5];
    float*       out   = (float*)d_out;

    ripple_fused_kernel<<<NB / 2, 256>>>(items, heads, rels, tails, ent, relm, out);
}

// round 10
// speedup vs baseline: 1.1338x; 1.1338x over previous
#include <cuda_runtime.h>
#include <math.h>

#define NH 2
#define NB 2048
#define NM 64
#define ND 16
#define NREL 32

// Fused kernel: 1024 blocks x 128 threads; each block handles 2 b's.
// Phase A: warp-cooperative q-precompute. Warp w owns relations 8w..8w+7.
//          Each relation read via 2 coalesced warp-wide LDG.128 (4 lines each),
//          shared across both bb accumulators; shfl-reduced over stride-4 lanes.
// Phase B (x2 sequential): R3/R7-proven quad-split gathers + softmax.
__global__ __launch_bounds__(128)
void ripple_fused_kernel(const int* __restrict__ items,
                         const int* __restrict__ heads,
                         const int* __restrict__ rels,
                         const int* __restrict__ tails,
                         const float* __restrict__ ent,
                         const float* __restrict__ relm,
                         float* __restrict__ out)
{
    const int b0   = blockIdx.x * 2;
    const int t    = threadIdx.x;      // 0..127
    const int lane = t & 31;
    const int wid  = t >> 5;           // 0..3
    const int sub  = t & 3;            // position within quad
    const int quad = t >> 2;           // 0..31

    __shared__ __align__(16) float  item_s[2][ND];
    __shared__ __align__(16) float4 q_s[2][NREL * 4];   // [bb][r*4+jg]
    __shared__ float logit_s[NH * NM];
    __shared__ float td_s[NH * NM];
    __shared__ float red_s[8];

    // ---- Phase A0: load 2 item embeddings (32 floats) ----
    if (t < 2 * ND) {
        const int bb = t >> 4;
        const int d  = t & 15;
        item_s[bb][d] = ent[(size_t)items[b0 + bb] * ND + d];
    }
    __syncthreads();

    // ---- Phase A1: warp-cooperative coalesced q-precompute ----
    // lane ℓ covers (i = ℓ>>2 [+8 for second half], jg = ℓ&3); float4 = q[r][jg*4..+3]
    {
        const float4* relm4 = (const float4*)relm;
        const int i0 = lane >> 2;
        const float s00 = item_s[0][i0];
        const float s01 = item_s[0][i0 + 8];
        const float s10 = item_s[1][i0];
        const float s11 = item_s[1][i0 + 8];

        #pragma unroll
        for (int rr = 0; rr < 8; rr++) {
            const int r = wid * 8 + rr;
            float4 Rv0 = relm4[r * 64 + lane];        // i = lane>>2
            float4 Rv1 = relm4[r * 64 + 32 + lane];   // i = 8 + lane>>2

            float4 a0, a1;
            a0.x = s00 * Rv0.x + s01 * Rv1.x;
            a0.y = s00 * Rv0.y + s01 * Rv1.y;
            a0.z = s00 * Rv0.z + s01 * Rv1.z;
            a0.w = s00 * Rv0.w + s01 * Rv1.w;
            a1.x = s10 * Rv0.x + s11 * Rv1.x;
            a1.y = s10 * Rv0.y + s11 * Rv1.y;
            a1.z = s10 * Rv0.z + s11 * Rv1.z;
            a1.w = s10 * Rv0.w + s11 * Rv1.w;

            #pragma unroll
            for (int o = 4; o <= 16; o <<= 1) {
                a0.x += __shfl_xor_sync(0xffffffffu, a0.x, o);
                a0.y += __shfl_xor_sync(0xffffffffu, a0.y, o);
                a0.z += __shfl_xor_sync(0xffffffffu, a0.z, o);
                a0.w += __shfl_xor_sync(0xffffffffu, a0.w, o);
                a1.x += __shfl_xor_sync(0xffffffffu, a1.x, o);
                a1.y += __shfl_xor_sync(0xffffffffu, a1.y, o);
                a1.z += __shfl_xor_sync(0xffffffffu, a1.z, o);
                a1.w += __shfl_xor_sync(0xffffffffu, a1.w, o);
            }
            if (lane < 4)      q_s[0][r * 4 + lane] = a0;
            else if (lane < 8) q_s[1][r * 4 + (lane & 3)] = a1;
        }
    }
    __syncthreads();

    const float4* ent4 = (const float4*)ent;

    // ---- Phase B: per-b gathers + softmax (R7-proven structure) ----
    for (int bb = 0; bb < 2; bb++) {
        const int b  = b0 + bb;
        const float4 iv = ((const float4*)item_s[bb])[sub];

        #pragma unroll
        for (int pass = 0; pass < 4; pass++) {
            const int s    = pass * 32 + quad;       // slot 0..127
            const int hop  = s >> 6;
            const int m    = s & 63;
            const int gidx = hop * (NB * NM) + b * NM + m;

            const int hidx = heads[gidx];
            const int ridx = rels[gidx];
            const int tidx = tails[gidx];

            float4 hv = ent4[(size_t)hidx * 4 + sub];
            float4 tv = ent4[(size_t)tidx * 4 + sub];
            float4 qv = q_s[bb][ridx * 4 + sub];

            float pl = qv.x * hv.x + qv.y * hv.y + qv.z * hv.z + qv.w * hv.w;
            float pt = iv.x * tv.x + iv.y * tv.y + iv.z * tv.z + iv.w * tv.w;

            pl += __shfl_xor_sync(0xffffffffu, pl, 1);
            pl += __shfl_xor_sync(0xffffffffu, pl, 2);
            pt += __shfl_xor_sync(0xffffffffu, pt, 1);
            pt += __shfl_xor_sync(0xffffffffu, pt, 2);

            logit_s[s] = pl;
            td_s[s]    = pt;
        }
        __syncthreads();

        const int hop = t >> 6;
        float logit = logit_s[t];
        float td    = td_s[t];

        float mx = logit;
        #pragma unroll
        for (int o = 16; o > 0; o >>= 1)
            mx = fmaxf(mx, __shfl_xor_sync(0xffffffffu, mx, o));
        if (lane == 0) red_s[wid] = mx;
        __syncthreads();
        mx = fmaxf(red_s[hop * 2], red_s[hop * 2 + 1]);

        float e = __expf(logit - mx);
        float sm = e;
        #pragma unroll
        for (int o = 16; o > 0; o >>= 1)
            sm += __shfl_xor_sync(0xffffffffu, sm, o);
        if (lane == 0) red_s[4 + wid] = sm;
        __syncthreads();
        sm = red_s[4 + hop * 2] + red_s[4 + hop * 2 + 1];

        const float pi = e / sm;

        float c = pi * td;
        #pragma unroll
        for (int o = 16; o > 0; o >>= 1)
            c += __shfl_xor_sync(0xffffffffu, c, o);
        __syncthreads();                 // protect red_s reuse
        if (lane == 0) red_s[wid] = c;
        __syncthreads();

        if (t == 0) {
            float total = red_s[0] + red_s[1] + red_s[2] + red_s[3];
            out[b] = 1.f / (1.f + __expf(-total));
        }
        __syncthreads();                 // out-read of red_s before next bb
    }
}

extern "C" void kernel_launch(void* const* d_in, const int* in_sizes, int n_in,
                              void* d_out, int out_size)
{
    const int*   items = (const int*)d_in[0];
    const int*   heads = (const int*)d_in[1];
    const int*   rels  = (const int*)d_in[2];
    const int*   tails = (const int*)d_in[3];
    const float* ent   = (const float*)d_in[4];
    const float* relm  = (const float*)d_in[5];
    float*       out   = (float*)d_out;

    ripple_fused_kernel<<<NB / 2, 128>>>(items, heads, rels, tails, ent, relm, out);
}

// round 12
// speedup vs baseline: 1.3120x; 1.1572x over previous
#include <cuda_runtime.h>
#include <math.h>

#define NH 2
#define NB 2048
#define NM 64
#define ND 16
#define NREL 32

// Fused kernel: 1024 blocks x 128 threads; each block handles 2 b's.
// Phase A: R7-proven q-precompute (thread t owns (r,jg), float4 relm reads
//          shared across both bb accumulators).
// Phase B: ALL 8 gather passes (both b's) in one barrier-free unrolled loop,
//          then both softmaxes computed simultaneously (shared barriers).
__global__ __launch_bounds__(128)
void ripple_fused_kernel(const int* __restrict__ items,
                         const int* __restrict__ heads,
                         const int* __restrict__ rels,
                         const int* __restrict__ tails,
                         const float* __restrict__ ent,
                         const float* __restrict__ relm,
                         float* __restrict__ out)
{
    const int b0   = blockIdx.x * 2;
    const int t    = threadIdx.x;      // 0..127
    const int lane = t & 31;
    const int wid  = t >> 5;           // 0..3
    const int sub  = t & 3;            // position within quad
    const int quad = t >> 2;           // 0..31

    __shared__ __align__(16) float  item_s[2][ND];
    __shared__ __align__(16) float4 q_s[2][NREL * 4];   // [bb][r*4+jg]
    __shared__ float logit_s[2][NH * NM];
    __shared__ float td_s[2][NH * NM];
    __shared__ float red_s[2][8];

    // ---- Phase A0: load 2 item embeddings ----
    if (t < 2 * ND) {
        const int bb = t >> 4;
        const int d  = t & 15;
        item_s[bb][d] = ent[(size_t)items[b0 + bb] * ND + d];
    }
    __syncthreads();

    // ---- Phase A1: q-precompute (R7-proven); thread t owns (r = t>>2, jg = t&3) ----
    {
        const int r  = t >> 2;
        const int jg = t & 3;
        const float4* relm4 = (const float4*)relm;

        float4 a0 = make_float4(0.f, 0.f, 0.f, 0.f);
        float4 a1 = make_float4(0.f, 0.f, 0.f, 0.f);
        #pragma unroll
        for (int i = 0; i < ND; i++) {
            float4 Rv = relm4[r * 64 + i * 4 + jg];   // R[r][i][jg*4..+3]
            float s0 = item_s[0][i];
            float s1 = item_s[1][i];
            a0.x += s0 * Rv.x; a0.y += s0 * Rv.y; a0.z += s0 * Rv.z; a0.w += s0 * Rv.w;
            a1.x += s1 * Rv.x; a1.y += s1 * Rv.y; a1.z += s1 * Rv.z; a1.w += s1 * Rv.w;
        }
        q_s[0][t] = a0;    // t == r*4+jg
        q_s[1][t] = a1;
    }
    __syncthreads();

    const float4* ent4 = (const float4*)ent;
    const float4  iv0  = ((const float4*)item_s[0])[sub];
    const float4  iv1  = ((const float4*)item_s[1])[sub];

    // ---- Phase B1: all 8 passes (2 b's x 4 passes), no intermediate barrier ----
    #pragma unroll
    for (int it = 0; it < 8; it++) {
        const int bb   = it & 1;
        const int p    = it >> 1;
        const int s    = p * 32 + quad;          // slot 0..127
        const int hop  = s >> 6;
        const int m    = s & 63;
        const int gidx = hop * (NB * NM) + (b0 + bb) * NM + m;

        const int hidx = heads[gidx];
        const int ridx = rels[gidx];
        const int tidx = tails[gidx];

        float4 hv = ent4[(size_t)hidx * 4 + sub];
        float4 tv = ent4[(size_t)tidx * 4 + sub];
        float4 qv = q_s[bb][ridx * 4 + sub];
        const float4 iv = bb ? iv1 : iv0;

        float pl = qv.x * hv.x + qv.y * hv.y + qv.z * hv.z + qv.w * hv.w;
        float pt = iv.x * tv.x + iv.y * tv.y + iv.z * tv.z + iv.w * tv.w;

        pl += __shfl_xor_sync(0xffffffffu, pl, 1);
        pl += __shfl_xor_sync(0xffffffffu, pl, 2);
        pt += __shfl_xor_sync(0xffffffffu, pt, 1);
        pt += __shfl_xor_sync(0xffffffffu, pt, 2);

        logit_s[bb][s] = pl;
        td_s[bb][s]    = pt;
    }
    __syncthreads();

    // ---- Phase B2: both softmaxes simultaneously; thread t owns slot t of each bb ----
    const int hop = t >> 6;
    float l0 = logit_s[0][t], l1 = logit_s[1][t];
    float d0 = td_s[0][t],    d1 = td_s[1][t];

    float mx0 = l0, mx1 = l1;
    #pragma unroll
    for (int o = 16; o > 0; o >>= 1) {
        mx0 = fmaxf(mx0, __shfl_xor_sync(0xffffffffu, mx0, o));
        mx1 = fmaxf(mx1, __shfl_xor_sync(0xffffffffu, mx1, o));
    }
    if (lane == 0) { red_s[0][wid] = mx0; red_s[1][wid] = mx1; }
    __syncthreads();
    mx0 = fmaxf(red_s[0][hop * 2], red_s[0][hop * 2 + 1]);
    mx1 = fmaxf(red_s[1][hop * 2], red_s[1][hop * 2 + 1]);

    float e0 = __expf(l0 - mx0);
    float e1 = __expf(l1 - mx1);
    float sm0 = e0, sm1 = e1;
    #pragma unroll
    for (int o = 16; o > 0; o >>= 1) {
        sm0 += __shfl_xor_sync(0xffffffffu, sm0, o);
        sm1 += __shfl_xor_sync(0xffffffffu, sm1, o);
    }
    if (lane == 0) { red_s[0][4 + wid] = sm0; red_s[1][4 + wid] = sm1; }
    __syncthreads();
    sm0 = red_s[0][4 + hop * 2] + red_s[0][4 + hop * 2 + 1];
    sm1 = red_s[1][4 + hop * 2] + red_s[1][4 + hop * 2 + 1];

    // ---- contributions for both b's; block-reduce ----
    float c0 = (e0 / sm0) * d0;
    float c1 = (e1 / sm1) * d1;
    #pragma unroll
    for (int o = 16; o > 0; o >>= 1) {
        c0 += __shfl_xor_sync(0xffffffffu, c0, o);
        c1 += __shfl_xor_sync(0xffffffffu, c1, o);
    }
    __syncthreads();                 // protect red_s reuse
    if (lane == 0) { red_s[0][wid] = c0; red_s[1][wid] = c1; }
    __syncthreads();

    if (t < 2) {
        float total = red_s[t][0] + red_s[t][1] + red_s[t][2] + red_s[t][3];
        out[b0 + t] = 1.f / (1.f + __expf(-total));
    }
}

extern "C" void kernel_launch(void* const* d_in, const int* in_sizes, int n_in,
                              void* d_out, int out_size)
{
    const int*   items = (const int*)d_in[0];
    const int*   heads = (const int*)d_in[1];
    const int*   rels  = (const int*)d_in[2];
    const int*   tails = (const int*)d_in[3];
    const float* ent   = (const float*)d_in[4];
    const float* relm  = (const float*)d_in[5];
    float*       out   = (float*)d_out;

    ripple_fused_kernel<<<NB / 2, 128>>>(items, heads, rels, tails, ent, relm, out);
}

// round 14
// speedup vs baseline: 1.3383x; 1.0201x over previous
#include <cuda_runtime.h>
#include <math.h>

#define NH 2
#define NB 2048
#define NM 64
#define ND 16
#define NREL 32

// Fused kernel: 512 blocks x 256 threads; each block handles 4 b's.
// Phase A: threads 0-127 own (r = t>>2, jg = t&3); each relm float4 load is
//          shared across FOUR bb accumulators (relm L2 traffic halved vs 2-b).
// Phase B: two independent half-blocks (warps 0-3 -> b's {0,1}; warps 4-7 ->
//          b's {2,3}), each running the R12-proven fused 8-pass gathers +
//          dual softmax. Barrier counts symmetric across halves.
__global__ __launch_bounds__(256)
void ripple_fused_kernel(const int* __restrict__ items,
                         const int* __restrict__ heads,
                         const int* __restrict__ rels,
                         const int* __restrict__ tails,
                         const float* __restrict__ ent,
                         const float* __restrict__ relm,
                         float* __restrict__ out)
{
    const int b0   = blockIdx.x * 4;
    const int t    = threadIdx.x;      // 0..255
    const int h    = t >> 7;           // half-block 0/1 -> b pair {2h, 2h+1}
    const int tl   = t & 127;          // thread-in-half
    const int lane = t & 31;
    const int widh = tl >> 5;          // warp-in-half 0..3
    const int sub  = t & 3;
    const int quad = tl >> 2;          // 0..31

    __shared__ __align__(16) float  item_s[4][ND];
    __shared__ __align__(16) float4 q_s[4][NREL * 4];   // [bb][r*4+jg]
    __shared__ float logit_s[4][NH * NM];
    __shared__ float td_s[4][NH * NM];
    __shared__ float red_s[4][8];

    // ---- Phase A0: load 4 item embeddings (64 floats) ----
    if (t < 4 * ND) {
        const int ib = t >> 4;
        const int d  = t & 15;
        item_s[ib][d] = ent[(size_t)items[b0 + ib] * ND + d];
    }
    __syncthreads();

    // ---- Phase A1: q-precompute; threads 0-127, 4 accumulators per relm load ----
    if (t < 128) {
        const int r  = t >> 2;
        const int jg = t & 3;
        const float4* relm4 = (const float4*)relm;

        float4 a0 = make_float4(0.f, 0.f, 0.f, 0.f);
        float4 a1 = make_float4(0.f, 0.f, 0.f, 0.f);
        float4 a2 = make_float4(0.f, 0.f, 0.f, 0.f);
        float4 a3 = make_float4(0.f, 0.f, 0.f, 0.f);
        #pragma unroll
        for (int i = 0; i < ND; i++) {
            float4 Rv = relm4[r * 64 + i * 4 + jg];   // R[r][i][jg*4..+3]
            float s0 = item_s[0][i];
            float s1 = item_s[1][i];
            float s2 = item_s[2][i];
            float s3 = item_s[3][i];
            a0.x += s0 * Rv.x; a0.y += s0 * Rv.y; a0.z += s0 * Rv.z; a0.w += s0 * Rv.w;
            a1.x += s1 * Rv.x; a1.y += s1 * Rv.y; a1.z += s1 * Rv.z; a1.w += s1 * Rv.w;
            a2.x += s2 * Rv.x; a2.y += s2 * Rv.y; a2.z += s2 * Rv.z; a2.w += s2 * Rv.w;
            a3.x += s3 * Rv.x; a3.y += s3 * Rv.y; a3.z += s3 * Rv.z; a3.w += s3 * Rv.w;
        }
        q_s[0][t] = a0;    // t == r*4+jg
        q_s[1][t] = a1;
        q_s[2][t] = a2;
        q_s[3][t] = a3;
    }
    __syncthreads();

    const float4* ent4 = (const float4*)ent;
    const int     bbase = 2 * h;                       // this half's first bb
    const float4  iv0   = ((const float4*)item_s[bbase])[sub];
    const float4  iv1   = ((const float4*)item_s[bbase + 1])[sub];

    // ---- Phase B1: 8 fused passes (2 b's x 4 passes), no intermediate barrier ----
    #pragma unroll
    for (int it = 0; it < 8; it++) {
        const int bb   = bbase + (it & 1);
        const int p    = it >> 1;
        const int s    = p * 32 + quad;          // slot 0..127
        const int hop  = s >> 6;
        const int m    = s & 63;
        const int gidx = hop * (NB * NM) + (b0 + bb) * NM + m;

        const int hidx = heads[gidx];
        const int ridx = rels[gidx];
        const int tidx = tails[gidx];

        float4 hv = ent4[(size_t)hidx * 4 + sub];
        float4 tv = ent4[(size_t)tidx * 4 + sub];
        float4 qv = q_s[bb][ridx * 4 + sub];
        const float4 iv = (it & 1) ? iv1 : iv0;

        float pl = qv.x * hv.x + qv.y * hv.y + qv.z * hv.z + qv.w * hv.w;
        float pt = iv.x * tv.x + iv.y * tv.y + iv.z * tv.z + iv.w * tv.w;

        pl += __shfl_xor_sync(0xffffffffu, pl, 1);
        pl += __shfl_xor_sync(0xffffffffu, pl, 2);
        pt += __shfl_xor_sync(0xffffffffu, pt, 1);
        pt += __shfl_xor_sync(0xffffffffu, pt, 2);

        logit_s[bb][s] = pl;
        td_s[bb][s]    = pt;
    }
    __syncthreads();

    // ---- Phase B2: both softmaxes of this half simultaneously ----
    const int hop = tl >> 6;
    float l0 = logit_s[bbase][tl],     l1 = logit_s[bbase + 1][tl];
    float d0 = td_s[bbase][tl],        d1 = td_s[bbase + 1][tl];

    float mx0 = l0, mx1 = l1;
    #pragma unroll
    for (int o = 16; o > 0; o >>= 1) {
        mx0 = fmaxf(mx0, __shfl_xor_sync(0xffffffffu, mx0, o));
        mx1 = fmaxf(mx1, __shfl_xor_sync(0xffffffffu, mx1, o));
    }
    if (lane == 0) { red_s[bbase][widh] = mx0; red_s[bbase + 1][widh] = mx1; }
    __syncthreads();
    mx0 = fmaxf(red_s[bbase][hop * 2],     red_s[bbase][hop * 2 + 1]);
    mx1 = fmaxf(red_s[bbase + 1][hop * 2], red_s[bbase + 1][hop * 2 + 1]);

    float e0 = __expf(l0 - mx0);
    float e1 = __expf(l1 - mx1);
    float sm0 = e0, sm1 = e1;
    #pragma unroll
    for (int o = 16; o > 0; o >>= 1) {
        sm0 += __shfl_xor_sync(0xffffffffu, sm0, o);
        sm1 += __shfl_xor_sync(0xffffffffu, sm1, o);
    }
    if (lane == 0) { red_s[bbase][4 + widh] = sm0; red_s[bbase + 1][4 + widh] = sm1; }
    __syncthreads();
    sm0 = red_s[bbase][4 + hop * 2]     + red_s[bbase][4 + hop * 2 + 1];
    sm1 = red_s[bbase + 1][4 + hop * 2] + red_s[bbase + 1][4 + hop * 2 + 1];

    // ---- contributions; reduce over this half's 128 threads ----
    float c0 = (e0 / sm0) * d0;
    float c1 = (e1 / sm1) * d1;
    #pragma unroll
    for (int o = 16; o > 0; o >>= 1) {
        c0 += __shfl_xor_sync(0xffffffffu, c0, o);
        c1 += __shfl_xor_sync(0xffffffffu, c1, o);
    }
    __syncthreads();                 // protect red_s reuse
    if (lane == 0) { red_s[bbase][widh] = c0; red_s[bbase + 1][widh] = c1; }
    __syncthreads();

    if (tl < 2) {
        const int bb = bbase + tl;
        float total = red_s[bb][0] + red_s[bb][1] + red_s[bb][2] + red_s[bb][3];
        out[b0 + bb] = 1.f / (1.f + __expf(-total));
    }
}

extern "C" void kernel_launch(void* const* d_in, const int* in_sizes, int n_in,
                              void* d_out, int out_size)
{
    const int*   items = (const int*)d_in[0];
    const int*   heads = (const int*)d_in[1];
    const int*   rels  = (const int*)d_in[2];
    const int*   tails = (const int*)d_in[3];
    const float* ent   = (const float*)d_in[4];
    const float* relm  = (const float*)d_in[5];
    float*       out   = (float*)d_out;

    ripple_fused_kernel<<<NB / 4, 256>>>(items, heads, rels, tails, ent, relm, out);
}